// round 12
// baseline (speedup 1.0000x reference)
#include <cuda_runtime.h>
#include <cuda_fp16.h>
#include <cstdint>
#include <math.h>

// Fixed shapes
#define Sd   2048
#define Dd   2048
#define Hd   16
#define HDd  128
#define NTOK 4096            // B*S
#define BH   32              // B*H

// ---------------------------------------------------------------------------
// Device scratch
// ---------------------------------------------------------------------------
__device__ __align__(16) __half g_hs16[(long)NTOK * Dd];
__device__ __align__(16) __half g_w16[(long)4 * Dd * Dd];       // Wq,Wk,Wv,Wo
__device__ __align__(16) __half g_q16[(long)BH * Sd * HDd];     // [bh][s][hd]
__device__ __align__(16) __half g_k16[(long)BH * Sd * HDd];     // [bh][t][hd]
__device__ __align__(16) __half g_vT16[(long)BH * HDd * Sd];    // [bh][hd][t]
__device__ __align__(16) __half g_ctx16[(long)NTOK * Dd];       // [b,s,D]
__device__ __align__(8)  float2 g_rope[(long)Sd * 64];          // (sin,cos)

// dataflow readiness counters (zeroed by k_prep each launch)
__device__ int g_head_cnt[BH];   // (b*16+h): 48 QKV tiles each
__device__ int g_ctx_cnt[32];    // (b*16+blk): 16 fattn items each

__device__ __forceinline__ uint32_t smem_to_u32(const void* p) {
    uint32_t a;
    asm("{ .reg .u64 t; cvta.to.shared.u64 t, %1; cvt.u32.u64 %0, t; }" : "=r"(a) : "l"(p));
    return a;
}

// ---------------------------------------------------------------------------
// Fused prep: converts (16 floats/thread) + RoPE table + counter reset.
// ---------------------------------------------------------------------------
__global__ void __launch_bounds__(256) k_prep(const float* __restrict__ hs,
                                              const float* __restrict__ Wq,
                                              const float* __restrict__ Wk,
                                              const float* __restrict__ Wv,
                                              const float* __restrict__ Wo) {
    const int b = blockIdx.x, tid = threadIdx.x;
    if (b == 0 && tid < 64) {   // zero flags for this launch
        if (tid < 32) g_head_cnt[tid] = 0;
        else          g_ctx_cnt[tid - 32] = 0;
    }
    if (b < 6144) {
        const float* src;
        __half* dst;
        long base;
        if (b < 2048)      { src = hs; dst = g_hs16;                    base = (long)b * 4096; }
        else if (b < 3072) { src = Wq; dst = g_w16;                     base = (long)(b - 2048) * 4096; }
        else if (b < 4096) { src = Wk; dst = g_w16 + (long)Dd * Dd;     base = (long)(b - 3072) * 4096; }
        else if (b < 5120) { src = Wv; dst = g_w16 + (long)2 * Dd * Dd; base = (long)(b - 4096) * 4096; }
        else               { src = Wo; dst = g_w16 + (long)3 * Dd * Dd; base = (long)(b - 5120) * 4096; }
        const long i = base + tid * 16;
        float4 x0 = *(const float4*)(src + i);
        float4 x1 = *(const float4*)(src + i + 4);
        float4 x2 = *(const float4*)(src + i + 8);
        float4 x3 = *(const float4*)(src + i + 12);
        __half2 h0 = __floats2half2_rn(x0.x, x0.y), h1 = __floats2half2_rn(x0.z, x0.w);
        __half2 h2 = __floats2half2_rn(x1.x, x1.y), h3 = __floats2half2_rn(x1.z, x1.w);
        __half2 h4 = __floats2half2_rn(x2.x, x2.y), h5 = __floats2half2_rn(x2.z, x2.w);
        __half2 h6 = __floats2half2_rn(x3.x, x3.y), h7 = __floats2half2_rn(x3.z, x3.w);
        uint4 o0, o1;
        o0.x = *(uint32_t*)&h0; o0.y = *(uint32_t*)&h1;
        o0.z = *(uint32_t*)&h2; o0.w = *(uint32_t*)&h3;
        o1.x = *(uint32_t*)&h4; o1.y = *(uint32_t*)&h5;
        o1.z = *(uint32_t*)&h6; o1.w = *(uint32_t*)&h7;
        *(uint4*)(dst + i)     = o0;
        *(uint4*)(dst + i + 8) = o1;
    } else {
        const int idx = (b - 6144) * 256 + tid;
        const int s = idx >> 6, j = idx & 63;
        const float inv = 1.0f / powf(10000.0f, (float)j * (1.0f / 64.0f));
        float sn, cs;
        sincosf((float)s * inv, &sn, &cs);
        g_rope[idx] = make_float2(sn, cs);
    }
}

// ---------------------------------------------------------------------------
// Persistent HMMA GEMM — R7/R11 config. mode 0: QKV (head-major order,
// signals g_head_cnt). mode 5: out-proj (ctx-order tiles, spins g_ctx_cnt).
// ---------------------------------------------------------------------------
#define BKt 64
#define STG_BYTES (256 * BKt * 2)           // 32768
#define GEMM_SMEM (3 * STG_BYTES)           // 98304

__global__ void __launch_bounds__(256, 2) k_hgemm(
    const float* __restrict__ bq_, const float* __restrict__ bk_,
    const float* __restrict__ bv_, float* __restrict__ outp, int mode, int NT) {
    extern __shared__ char smem[];
    __shared__ float bias_s[128];
    const uint32_t sb = smem_to_u32(smem);
    const int tid = threadIdx.x, lane = tid & 31, wid = tid >> 5;
    const int wm = wid >> 2, wn = wid & 3;

    for (int t = blockIdx.x; t < NT; t += gridDim.x) {
        int x, y, z;
        if (mode == 0) {
            // head-major: x slowest so heads complete as early as possible
            x = t / 96;
            const int r = t % 96;
            z = r >> 5;
            y = r & 31;
        } else {
            // ctx completion order: blk fast-ish, matching fattn item order
            x = t & 15;
            const int yy = t >> 4;
            const int blk = yy >> 1, bb = yy & 1;
            y = bb * 16 + blk;
            z = 3;
        }
        const int m0 = y * 128, n0 = x * 128;
        const __half* Ap = ((mode == 0) ? g_hs16 : g_ctx16) + (long)m0 * Dd;
        const __half* Bp = g_w16 + (long)z * Dd * Dd + (long)n0 * Dd;
        const float* bias = (mode == 0) ? (z == 0 ? bq_ : z == 1 ? bk_ : bv_) : bq_;

        if (mode == 5) {
            // wait until all 16 heads wrote this ctx row-block
            if (tid == 0) {
                while (((volatile int*)g_ctx_cnt)[y] < 16) {}
                __threadfence();
            }
        }
        __syncthreads();
        if (tid < 128) bias_s[tid] = bias[n0 + tid];

        auto load_stage = [&](int st, int k0) {
            const uint32_t base = sb + (uint32_t)st * STG_BYTES;
#pragma unroll
            for (int i = 0; i < 4; i++) {
                const int id = tid + i * 256;
                const int row = id >> 3, ch = id & 7;
                uint32_t off = (uint32_t)(row * 128 + ch * 16);
                uint32_t dst = base + (off ^ ((off >> 3) & 0x70));
                const __half* g = Ap + (long)row * Dd + k0 + ch * 8;
                asm volatile("cp.async.cg.shared.global [%0], [%1], 16;" :: "r"(dst), "l"(g));
            }
#pragma unroll
            for (int i = 0; i < 4; i++) {
                const int id = tid + i * 256;
                const int row = id >> 3, ch = id & 7;
                uint32_t off = (uint32_t)(row * 128 + ch * 16);
                uint32_t dst = base + 16384 + (off ^ ((off >> 3) & 0x70));
                const __half* g = Bp + (long)row * Dd + k0 + ch * 8;
                asm volatile("cp.async.cg.shared.global [%0], [%1], 16;" :: "r"(dst), "l"(g));
            }
        };

        float c[4][4][4] = {};

        auto compute = [&](int st) {
            const uint32_t abase = sb + (uint32_t)st * STG_BYTES;
            const uint32_t bbase = abase + 16384;
#pragma unroll
            for (int kk = 0; kk < 4; kk++) {
                uint32_t a[4][4], b[4][2];
#pragma unroll
                for (int mi = 0; mi < 4; mi++) {
                    const int row = wm * 64 + mi * 16 + (lane & 15);
                    uint32_t off = (uint32_t)(row * 128 + kk * 32 + ((lane >> 4) << 4));
                    uint32_t ad = abase + (off ^ ((off >> 3) & 0x70));
                    asm volatile("ldmatrix.sync.aligned.m8n8.x4.shared.b16 {%0,%1,%2,%3}, [%4];"
                                 : "=r"(a[mi][0]), "=r"(a[mi][1]), "=r"(a[mi][2]), "=r"(a[mi][3])
                                 : "r"(ad));
                }
#pragma unroll
                for (int p = 0; p < 2; p++) {
                    const int g = lane >> 3;
                    const int row = wn * 32 + p * 16 + (g >> 1) * 8 + (lane & 7);
                    uint32_t off = (uint32_t)(row * 128 + kk * 32 + ((g & 1) << 4));
                    uint32_t bd = bbase + (off ^ ((off >> 3) & 0x70));
                    asm volatile("ldmatrix.sync.aligned.m8n8.x4.shared.b16 {%0,%1,%2,%3}, [%4];"
                                 : "=r"(b[2*p][0]), "=r"(b[2*p][1]),
                                   "=r"(b[2*p+1][0]), "=r"(b[2*p+1][1])
                                 : "r"(bd));
                }
#pragma unroll
                for (int mi = 0; mi < 4; mi++)
#pragma unroll
                    for (int ni = 0; ni < 4; ni++)
                        asm volatile(
                            "mma.sync.aligned.m16n8k16.row.col.f32.f16.f16.f32 "
                            "{%0,%1,%2,%3}, {%4,%5,%6,%7}, {%8,%9}, {%0,%1,%2,%3};"
                            : "+f"(c[mi][ni][0]), "+f"(c[mi][ni][1]),
                              "+f"(c[mi][ni][2]), "+f"(c[mi][ni][3])
                            : "r"(a[mi][0]), "r"(a[mi][1]), "r"(a[mi][2]), "r"(a[mi][3]),
                              "r"(b[ni][0]), "r"(b[ni][1]));
            }
        };

        load_stage(0, 0);
        asm volatile("cp.async.commit_group;" ::: "memory");
        load_stage(1, BKt);
        asm volatile("cp.async.commit_group;" ::: "memory");

        for (int c0 = 0; c0 < 32; c0++) {
            if (c0 < 31) asm volatile("cp.async.wait_group 1;" ::: "memory");
            else         asm volatile("cp.async.wait_group 0;" ::: "memory");
            __syncthreads();
            compute(c0 % 3);
            if (c0 + 2 < 32) {
                load_stage((c0 + 2) % 3, (c0 + 2) * BKt);
                asm volatile("cp.async.commit_group;" ::: "memory");
            }
        }

        if (mode == 5) {
#pragma unroll
            for (int mi = 0; mi < 4; mi++) {
                const int r0 = m0 + wm * 64 + mi * 16 + (lane >> 2);
#pragma unroll
                for (int ni = 0; ni < 4; ni++) {
                    const int cc = wn * 32 + ni * 8 + (lane & 3) * 2;
                    const float b0 = bias_s[cc], b1 = bias_s[cc + 1];
                    float2 v0 = make_float2(c[mi][ni][0] + b0, c[mi][ni][1] + b1);
                    float2 v1 = make_float2(c[mi][ni][2] + b0, c[mi][ni][3] + b1);
                    *(float2*)(outp + (long)r0 * Dd + n0 + cc)       = v0;
                    *(float2*)(outp + (long)(r0 + 8) * Dd + n0 + cc) = v1;
                }
            }
        } else {
            float* sm = (float*)smem;  // [128][129]
            __syncthreads();
#pragma unroll
            for (int mi = 0; mi < 4; mi++)
#pragma unroll
                for (int ni = 0; ni < 4; ni++) {
                    const int r0 = wm * 64 + mi * 16 + (lane >> 2);
                    const int cc = wn * 32 + ni * 8 + (lane & 3) * 2;
                    sm[r0 * 129 + cc]           = c[mi][ni][0] + bias_s[cc];
                    sm[r0 * 129 + cc + 1]       = c[mi][ni][1] + bias_s[cc + 1];
                    sm[(r0 + 8) * 129 + cc]     = c[mi][ni][2] + bias_s[cc];
                    sm[(r0 + 8) * 129 + cc + 1] = c[mi][ni][3] + bias_s[cc + 1];
                }
            __syncthreads();

            const int b = m0 >> 11, h = n0 >> 7;
            if (z < 2) {
                __half* out = (z == 0) ? g_q16 : g_k16;
                const long obase = ((long)(b * Hd + h) * Sd + (m0 & 2047)) * HDd;
                for (int idx = tid; idx < 128 * 64; idx += 256) {
                    const int r = idx >> 6, j = idx & 63;
                    const int s = (m0 & 2047) + r;
                    const float2 tc = g_rope[s * 64 + j];
                    const float lo = sm[r * 129 + j], hi = sm[r * 129 + j + 64];
                    out[obase + (long)r * HDd + j]      = __float2half(lo * tc.x - hi * tc.y);
                    out[obase + (long)r * HDd + j + 64] = __float2half(hi * tc.x + lo * tc.y);
                }
            } else {
                const long obase = (long)(b * Hd + h) * HDd * Sd;
                const int t0 = m0 & 2047;
                for (int idx = tid; idx < 128 * 128; idx += 256) {
                    const int hd = idx >> 7, tt = idx & 127;
                    g_vT16[obase + (long)hd * Sd + t0 + tt] = __float2half(sm[tt * 129 + hd]);
                }
            }
            // signal: this (b,h) got one more of its 48 tiles
            __threadfence();
            __syncthreads();
            if (tid == 0) atomicAdd(&g_head_cnt[b * 16 + h], 1);
        }
    }
}

// ---------------------------------------------------------------------------
// Persistent fused flash attention (R11 3-stage pipeline), item order
// (bh fast, blk slow) + head spin + ctx signal.
// ---------------------------------------------------------------------------
#define PITCH 272
#define TILEB (128 * PITCH)          // 34816
#define FA_SMEM (6 * TILEB)          // 208896
#define FA_NT  (16 * BH)             // 512

__global__ void __launch_bounds__(256, 1) k_fattn() {
    extern __shared__ char smem[];
    const uint32_t sb = smem_to_u32(smem);
    const int tid = threadIdx.x, lane = tid & 31, w = tid >> 5;

    auto kbase = [&](int i) { return sb + (uint32_t)i * TILEB; };
    auto vbase = [&](int i) { return sb + (uint32_t)(3 + i) * TILEB; };

    auto ldtile = [&](uint32_t base, const __half* g, int ldg) {
#pragma unroll
        for (int it = 0; it < 8; it++) {
            const int id = tid + it * 256;
            const int row = id >> 4, ch = id & 15;
            uint32_t dst = base + (uint32_t)(row * PITCH + ch * 16);
            const __half* src = g + (long)row * ldg + ch * 8;
            asm volatile("cp.async.cg.shared.global [%0], [%1], 16;" :: "r"(dst), "l"(src));
        }
    };

    for (int it = blockIdx.x; it < FA_NT; it += gridDim.x) {
        const int bh = it & 31, blk = it >> 5;
        const int m0 = blk * 128;
        const __half* Qp = g_q16 + (long)bh * Sd * HDd + (long)m0 * HDd;
        const __half* Kp = g_k16 + (long)bh * Sd * HDd;
        const __half* Vp = g_vT16 + (long)bh * HDd * Sd;

        // wait for this head's q/k/v to be complete (48 QKV tiles)
        if (tid == 0) {
            while (((volatile int*)g_head_cnt)[bh] < 48) {}
            __threadfence();
        }
        __syncthreads();   // also guards smem reuse from previous item

        // ---- Q tile -> smem (stage K0) -> registers ----
        ldtile(kbase(0), Qp, HDd);
        asm volatile("cp.async.commit_group;" ::: "memory");
        asm volatile("cp.async.wait_group 0;" ::: "memory");
        __syncthreads();

        uint32_t aq[8][4];
#pragma unroll
        for (int kk = 0; kk < 8; kk++) {
            const int row = w * 16 + (lane & 15);
            uint32_t ad = kbase(0) + (uint32_t)(row * PITCH + kk * 32 + ((lane >> 4) << 4));
            asm volatile("ldmatrix.sync.aligned.m8n8.x4.shared.b16 {%0,%1,%2,%3}, [%4];"
                         : "=r"(aq[kk][0]), "=r"(aq[kk][1]), "=r"(aq[kk][2]), "=r"(aq[kk][3])
                         : "r"(ad));
        }
        __syncthreads();

        float o[16][4] = {};
        float mr0 = -1e30f, mr1 = -1e30f, lr0 = 0.0f, lr1 = 0.0f;
        const float sc = 0.08838834764831845f;

        ldtile(kbase(0), Kp, HDd);
        ldtile(vbase(0), Vp, Sd);
        asm volatile("cp.async.commit_group;" ::: "memory");
        ldtile(kbase(1), Kp + (long)128 * HDd, HDd);
        ldtile(vbase(1), Vp + 128, Sd);
        asm volatile("cp.async.commit_group;" ::: "memory");

        for (int kt = 0; kt < 16; kt++) {
            const int buf = kt % 3;
            if (kt < 15) asm volatile("cp.async.wait_group 1;" ::: "memory");
            else         asm volatile("cp.async.wait_group 0;" ::: "memory");
            __syncthreads();

            float cS[16][4] = {};
#pragma unroll
            for (int kk = 0; kk < 8; kk++) {
#pragma unroll
                for (int p = 0; p < 8; p++) {
                    const int g = lane >> 3;
                    const int row = p * 16 + (g >> 1) * 8 + (lane & 7);
                    uint32_t bd = kbase(buf) + (uint32_t)(row * PITCH + kk * 32 + ((g & 1) << 4));
                    uint32_t b0, b1, b2, b3;
                    asm volatile("ldmatrix.sync.aligned.m8n8.x4.shared.b16 {%0,%1,%2,%3}, [%4];"
                                 : "=r"(b0), "=r"(b1), "=r"(b2), "=r"(b3) : "r"(bd));
                    asm volatile(
                        "mma.sync.aligned.m16n8k16.row.col.f32.f16.f16.f32 "
                        "{%0,%1,%2,%3}, {%4,%5,%6,%7}, {%8,%9}, {%0,%1,%2,%3};"
                        : "+f"(cS[2*p][0]), "+f"(cS[2*p][1]), "+f"(cS[2*p][2]), "+f"(cS[2*p][3])
                        : "r"(aq[kk][0]), "r"(aq[kk][1]), "r"(aq[kk][2]), "r"(aq[kk][3]),
                          "r"(b0), "r"(b1));
                    asm volatile(
                        "mma.sync.aligned.m16n8k16.row.col.f32.f16.f16.f32 "
                        "{%0,%1,%2,%3}, {%4,%5,%6,%7}, {%8,%9}, {%0,%1,%2,%3};"
                        : "+f"(cS[2*p+1][0]), "+f"(cS[2*p+1][1]), "+f"(cS[2*p+1][2]), "+f"(cS[2*p+1][3])
                        : "r"(aq[kk][0]), "r"(aq[kk][1]), "r"(aq[kk][2]), "r"(aq[kk][3]),
                          "r"(b2), "r"(b3));
                }
            }

            float mx0 = -1e30f, mx1 = -1e30f;
#pragma unroll
            for (int ni = 0; ni < 16; ni++) {
                mx0 = fmaxf(mx0, fmaxf(cS[ni][0], cS[ni][1]));
                mx1 = fmaxf(mx1, fmaxf(cS[ni][2], cS[ni][3]));
            }
            mx0 = fmaxf(mx0, __shfl_xor_sync(0xffffffffu, mx0, 1));
            mx0 = fmaxf(mx0, __shfl_xor_sync(0xffffffffu, mx0, 2));
            mx1 = fmaxf(mx1, __shfl_xor_sync(0xffffffffu, mx1, 1));
            mx1 = fmaxf(mx1, __shfl_xor_sync(0xffffffffu, mx1, 2));

            const float mn0 = fmaxf(mr0, mx0), mn1 = fmaxf(mr1, mx1);
            const float al0 = __expf((mr0 - mn0) * sc), al1 = __expf((mr1 - mn1) * sc);
            mr0 = mn0; mr1 = mn1;

            uint32_t pr0[16], pr1[16];
            float s0 = 0.0f, s1 = 0.0f;
#pragma unroll
            for (int ni = 0; ni < 16; ni++) {
                const float p0 = __expf((cS[ni][0] - mn0) * sc);
                const float p1 = __expf((cS[ni][1] - mn0) * sc);
                const float p2 = __expf((cS[ni][2] - mn1) * sc);
                const float p3 = __expf((cS[ni][3] - mn1) * sc);
                s0 += p0 + p1; s1 += p2 + p3;
                __half2 h0 = __floats2half2_rn(p0, p1);
                __half2 h1 = __floats2half2_rn(p2, p3);
                pr0[ni] = *(uint32_t*)&h0;
                pr1[ni] = *(uint32_t*)&h1;
            }
            s0 += __shfl_xor_sync(0xffffffffu, s0, 1);
            s0 += __shfl_xor_sync(0xffffffffu, s0, 2);
            s1 += __shfl_xor_sync(0xffffffffu, s1, 1);
            s1 += __shfl_xor_sync(0xffffffffu, s1, 2);
            lr0 = lr0 * al0 + s0;
            lr1 = lr1 * al1 + s1;

#pragma unroll
            for (int ni = 0; ni < 16; ni++) {
                o[ni][0] *= al0; o[ni][1] *= al0;
                o[ni][2] *= al1; o[ni][3] *= al1;
            }

#pragma unroll
            for (int kf = 0; kf < 8; kf++) {
                const uint32_t a0 = pr0[2 * kf], a1 = pr1[2 * kf];
                const uint32_t a2 = pr0[2 * kf + 1], a3 = pr1[2 * kf + 1];
#pragma unroll
                for (int p = 0; p < 8; p++) {
                    const int g = lane >> 3;
                    const int row = p * 16 + (g >> 1) * 8 + (lane & 7);
                    uint32_t bd = vbase(buf) + (uint32_t)(row * PITCH + kf * 32 + ((g & 1) << 4));
                    uint32_t b0, b1, b2, b3;
                    asm volatile("ldmatrix.sync.aligned.m8n8.x4.shared.b16 {%0,%1,%2,%3}, [%4];"
                                 : "=r"(b0), "=r"(b1), "=r"(b2), "=r"(b3) : "r"(bd));
                    asm volatile(
                        "mma.sync.aligned.m16n8k16.row.col.f32.f16.f16.f32 "
                        "{%0,%1,%2,%3}, {%4,%5,%6,%7}, {%8,%9}, {%0,%1,%2,%3};"
                        : "+f"(o[2*p][0]), "+f"(o[2*p][1]), "+f"(o[2*p][2]), "+f"(o[2*p][3])
                        : "r"(a0), "r"(a1), "r"(a2), "r"(a3), "r"(b0), "r"(b1));
                    asm volatile(
                        "mma.sync.aligned.m16n8k16.row.col.f32.f16.f16.f32 "
                        "{%0,%1,%2,%3}, {%4,%5,%6,%7}, {%8,%9}, {%0,%1,%2,%3};"
                        : "+f"(o[2*p+1][0]), "+f"(o[2*p+1][1]), "+f"(o[2*p+1][2]), "+f"(o[2*p+1][3])
                        : "r"(a0), "r"(a1), "r"(a2), "r"(a3), "r"(b2), "r"(b3));
                }
            }

            if (kt + 2 < 16) {
                const int nb = (kt + 2) % 3;
                ldtile(kbase(nb), Kp + (long)(kt + 2) * 128 * HDd, HDd);
                ldtile(vbase(nb), Vp + (kt + 2) * 128, Sd);
                asm volatile("cp.async.commit_group;" ::: "memory");
            }
        }

        // ---- epilogue ----
        const int b = bh >> 4, h = bh & 15;
        const float i0 = 1.0f / lr0, i1 = 1.0f / lr1;
        const int r0 = m0 + w * 16 + (lane >> 2);
        const long base0 = (long)b * Sd * Dd + (long)r0 * Dd + h * HDd + (lane & 3) * 2;
        const long base1 = base0 + 8 * Dd;
#pragma unroll
        for (int ni = 0; ni < 16; ni++) {
            __half2 h0 = __floats2half2_rn(o[ni][0] * i0, o[ni][1] * i0);
            __half2 h1 = __floats2half2_rn(o[ni][2] * i1, o[ni][3] * i1);
            *(__half2*)(g_ctx16 + base0 + ni * 8) = h0;
            *(__half2*)(g_ctx16 + base1 + ni * 8) = h1;
        }

        // signal: ctx row-block (b, blk) got one of its 16 head-slices
        __threadfence();
        __syncthreads();
        if (tid == 0) atomicAdd(&g_ctx_cnt[b * 16 + blk], 1);
    }
}

// ---------------------------------------------------------------------------
extern "C" void kernel_launch(void* const* d_in, const int* in_sizes, int n_in,
                              void* d_out, int out_size) {
    const float* hs = (const float*)d_in[0];
    const float* Wq = (const float*)d_in[1];
    const float* bq = (const float*)d_in[2];
    const float* Wk = (const float*)d_in[3];
    const float* bk = (const float*)d_in[4];
    const float* Wv = (const float*)d_in[5];
    const float* bv = (const float*)d_in[6];
    const float* Wo = (const float*)d_in[7];
    const float* bo = (const float*)d_in[8];
    float* out = (float*)d_out;

    static int sms = 0;
    if (!sms) {
        cudaDeviceGetAttribute(&sms, cudaDevAttrMultiProcessorCount, 0);
        cudaFuncSetAttribute(k_hgemm, cudaFuncAttributeMaxDynamicSharedMemorySize, GEMM_SMEM);
        cudaFuncSetAttribute(k_fattn, cudaFuncAttributeMaxDynamicSharedMemorySize, FA_SMEM);
    }

    k_prep<<<6656, 256>>>(hs, Wq, Wk, Wv, Wo);
    k_hgemm<<<2 * sms, 256, GEMM_SMEM>>>(bq, bk, bv, nullptr, 0, 1536);
    k_fattn<<<sms, 256, FA_SMEM>>>();
    k_hgemm<<<2 * sms, 256, GEMM_SMEM>>>(bo, nullptr, nullptr, out, 5, 512);
}

// round 13
// speedup vs baseline: 1.0517x; 1.0517x over previous
#include <cuda_runtime.h>
#include <cuda_fp16.h>
#include <cstdint>
#include <math.h>

// Fixed shapes
#define Sd   2048
#define Dd   2048
#define Hd   16
#define HDd  128
#define NTOK 4096            // B*S
#define BH   32              // B*H

// ---------------------------------------------------------------------------
// Device scratch
// ---------------------------------------------------------------------------
__device__ __align__(16) __half g_hs16[(long)NTOK * Dd];
__device__ __align__(16) __half g_w16[(long)4 * Dd * Dd];       // Wq,Wk,Wv,Wo
__device__ __align__(16) __half g_q16[(long)BH * Sd * HDd];     // [bh][s][hd], pre-scaled by sc*log2e
__device__ __align__(16) __half g_k16[(long)BH * Sd * HDd];     // [bh][t][hd]
__device__ __align__(16) __half g_vT16[(long)BH * HDd * Sd];    // [bh][hd][t]
__device__ __align__(16) __half g_ctx16[(long)NTOK * Dd];       // [b,s,D]
__device__ __align__(8)  float2 g_rope[(long)Sd * 64];          // (sin,cos)

__device__ __forceinline__ uint32_t smem_to_u32(const void* p) {
    uint32_t a;
    asm("{ .reg .u64 t; cvta.to.shared.u64 t, %1; cvt.u32.u64 %0, t; }" : "=r"(a) : "l"(p));
    return a;
}

// ---------------------------------------------------------------------------
// Fused prep: converts (16 floats/thread) + RoPE table.
// ---------------------------------------------------------------------------
__global__ void __launch_bounds__(256) k_prep(const float* __restrict__ hs,
                                              const float* __restrict__ Wq,
                                              const float* __restrict__ Wk,
                                              const float* __restrict__ Wv,
                                              const float* __restrict__ Wo) {
    const int b = blockIdx.x, tid = threadIdx.x;
    if (b < 6144) {
        const float* src;
        __half* dst;
        long base;
        if (b < 2048)      { src = hs; dst = g_hs16;                    base = (long)b * 4096; }
        else if (b < 3072) { src = Wq; dst = g_w16;                     base = (long)(b - 2048) * 4096; }
        else if (b < 4096) { src = Wk; dst = g_w16 + (long)Dd * Dd;     base = (long)(b - 3072) * 4096; }
        else if (b < 5120) { src = Wv; dst = g_w16 + (long)2 * Dd * Dd; base = (long)(b - 4096) * 4096; }
        else               { src = Wo; dst = g_w16 + (long)3 * Dd * Dd; base = (long)(b - 5120) * 4096; }
        const long i = base + tid * 16;
        float4 x0 = *(const float4*)(src + i);
        float4 x1 = *(const float4*)(src + i + 4);
        float4 x2 = *(const float4*)(src + i + 8);
        float4 x3 = *(const float4*)(src + i + 12);
        __half2 h0 = __floats2half2_rn(x0.x, x0.y), h1 = __floats2half2_rn(x0.z, x0.w);
        __half2 h2 = __floats2half2_rn(x1.x, x1.y), h3 = __floats2half2_rn(x1.z, x1.w);
        __half2 h4 = __floats2half2_rn(x2.x, x2.y), h5 = __floats2half2_rn(x2.z, x2.w);
        __half2 h6 = __floats2half2_rn(x3.x, x3.y), h7 = __floats2half2_rn(x3.z, x3.w);
        uint4 o0, o1;
        o0.x = *(uint32_t*)&h0; o0.y = *(uint32_t*)&h1;
        o0.z = *(uint32_t*)&h2; o0.w = *(uint32_t*)&h3;
        o1.x = *(uint32_t*)&h4; o1.y = *(uint32_t*)&h5;
        o1.z = *(uint32_t*)&h6; o1.w = *(uint32_t*)&h7;
        *(uint4*)(dst + i)     = o0;
        *(uint4*)(dst + i + 8) = o1;
    } else {
        const int idx = (b - 6144) * 256 + tid;
        const int s = idx >> 6, j = idx & 63;
        const float inv = 1.0f / powf(10000.0f, (float)j * (1.0f / 64.0f));
        float sn, cs;
        sincosf((float)s * inv, &sn, &cs);
        g_rope[idx] = make_float2(sn, cs);
    }
}

// ---------------------------------------------------------------------------
// Persistent HMMA GEMM — R7/R11 config (proven). The only change: q epilogue
// pre-scales by sc*log2(e) so fattn's softmax runs in the log2 domain.
// ---------------------------------------------------------------------------
#define BKt 64
#define STG_BYTES (256 * BKt * 2)           // 32768
#define GEMM_SMEM (3 * STG_BYTES)           // 98304
#define QSC 0.12751743f                     // (1/sqrt(128)) * log2(e)

__global__ void __launch_bounds__(256, 2) k_hgemm(
    const float* __restrict__ bq_, const float* __restrict__ bk_,
    const float* __restrict__ bv_, float* __restrict__ outp, int mode, int NT) {
    extern __shared__ char smem[];
    __shared__ float bias_s[128];
    const uint32_t sb = smem_to_u32(smem);
    const int tid = threadIdx.x, lane = tid & 31, wid = tid >> 5;
    const int wm = wid >> 2, wn = wid & 3;

    for (int t = blockIdx.x; t < NT; t += gridDim.x) {
        int x, y, z;
        if (mode == 0) { x = t & 15; y = (t >> 4) & 31; z = t >> 9; }
        else           { x = t & 15; y = t >> 4;        z = 3; }
        const int m0 = y * 128, n0 = x * 128;
        const __half* Ap = ((mode == 0) ? g_hs16 : g_ctx16) + (long)m0 * Dd;
        const __half* Bp = g_w16 + (long)z * Dd * Dd + (long)n0 * Dd;
        const float* bias = (mode == 0) ? (z == 0 ? bq_ : z == 1 ? bk_ : bv_) : bq_;

        __syncthreads();
        if (tid < 128) bias_s[tid] = bias[n0 + tid];

        auto load_stage = [&](int st, int k0) {
            const uint32_t base = sb + (uint32_t)st * STG_BYTES;
#pragma unroll
            for (int i = 0; i < 4; i++) {
                const int id = tid + i * 256;
                const int row = id >> 3, ch = id & 7;
                uint32_t off = (uint32_t)(row * 128 + ch * 16);
                uint32_t dst = base + (off ^ ((off >> 3) & 0x70));
                const __half* g = Ap + (long)row * Dd + k0 + ch * 8;
                asm volatile("cp.async.cg.shared.global [%0], [%1], 16;" :: "r"(dst), "l"(g));
            }
#pragma unroll
            for (int i = 0; i < 4; i++) {
                const int id = tid + i * 256;
                const int row = id >> 3, ch = id & 7;
                uint32_t off = (uint32_t)(row * 128 + ch * 16);
                uint32_t dst = base + 16384 + (off ^ ((off >> 3) & 0x70));
                const __half* g = Bp + (long)row * Dd + k0 + ch * 8;
                asm volatile("cp.async.cg.shared.global [%0], [%1], 16;" :: "r"(dst), "l"(g));
            }
        };

        float c[4][4][4] = {};

        auto compute = [&](int st) {
            const uint32_t abase = sb + (uint32_t)st * STG_BYTES;
            const uint32_t bbase = abase + 16384;
#pragma unroll
            for (int kk = 0; kk < 4; kk++) {
                uint32_t a[4][4], b[4][2];
#pragma unroll
                for (int mi = 0; mi < 4; mi++) {
                    const int row = wm * 64 + mi * 16 + (lane & 15);
                    uint32_t off = (uint32_t)(row * 128 + kk * 32 + ((lane >> 4) << 4));
                    uint32_t ad = abase + (off ^ ((off >> 3) & 0x70));
                    asm volatile("ldmatrix.sync.aligned.m8n8.x4.shared.b16 {%0,%1,%2,%3}, [%4];"
                                 : "=r"(a[mi][0]), "=r"(a[mi][1]), "=r"(a[mi][2]), "=r"(a[mi][3])
                                 : "r"(ad));
                }
#pragma unroll
                for (int p = 0; p < 2; p++) {
                    const int g = lane >> 3;
                    const int row = wn * 32 + p * 16 + (g >> 1) * 8 + (lane & 7);
                    uint32_t off = (uint32_t)(row * 128 + kk * 32 + ((g & 1) << 4));
                    uint32_t bd = bbase + (off ^ ((off >> 3) & 0x70));
                    asm volatile("ldmatrix.sync.aligned.m8n8.x4.shared.b16 {%0,%1,%2,%3}, [%4];"
                                 : "=r"(b[2*p][0]), "=r"(b[2*p][1]),
                                   "=r"(b[2*p+1][0]), "=r"(b[2*p+1][1])
                                 : "r"(bd));
                }
#pragma unroll
                for (int mi = 0; mi < 4; mi++)
#pragma unroll
                    for (int ni = 0; ni < 4; ni++)
                        asm volatile(
                            "mma.sync.aligned.m16n8k16.row.col.f32.f16.f16.f32 "
                            "{%0,%1,%2,%3}, {%4,%5,%6,%7}, {%8,%9}, {%0,%1,%2,%3};"
                            : "+f"(c[mi][ni][0]), "+f"(c[mi][ni][1]),
                              "+f"(c[mi][ni][2]), "+f"(c[mi][ni][3])
                            : "r"(a[mi][0]), "r"(a[mi][1]), "r"(a[mi][2]), "r"(a[mi][3]),
                              "r"(b[ni][0]), "r"(b[ni][1]));
            }
        };

        load_stage(0, 0);
        asm volatile("cp.async.commit_group;" ::: "memory");
        load_stage(1, BKt);
        asm volatile("cp.async.commit_group;" ::: "memory");

        for (int c0 = 0; c0 < 32; c0++) {
            if (c0 < 31) asm volatile("cp.async.wait_group 1;" ::: "memory");
            else         asm volatile("cp.async.wait_group 0;" ::: "memory");
            __syncthreads();
            compute(c0 % 3);
            if (c0 + 2 < 32) {
                load_stage((c0 + 2) % 3, (c0 + 2) * BKt);
                asm volatile("cp.async.commit_group;" ::: "memory");
            }
        }

        if (mode == 5) {
#pragma unroll
            for (int mi = 0; mi < 4; mi++) {
                const int r0 = m0 + wm * 64 + mi * 16 + (lane >> 2);
#pragma unroll
                for (int ni = 0; ni < 4; ni++) {
                    const int cc = wn * 32 + ni * 8 + (lane & 3) * 2;
                    const float b0 = bias_s[cc], b1 = bias_s[cc + 1];
                    float2 v0 = make_float2(c[mi][ni][0] + b0, c[mi][ni][1] + b1);
                    float2 v1 = make_float2(c[mi][ni][2] + b0, c[mi][ni][3] + b1);
                    *(float2*)(outp + (long)r0 * Dd + n0 + cc)       = v0;
                    *(float2*)(outp + (long)(r0 + 8) * Dd + n0 + cc) = v1;
                }
            }
        } else {
            float* sm = (float*)smem;  // [128][129]
            __syncthreads();
#pragma unroll
            for (int mi = 0; mi < 4; mi++)
#pragma unroll
                for (int ni = 0; ni < 4; ni++) {
                    const int r0 = wm * 64 + mi * 16 + (lane >> 2);
                    const int cc = wn * 32 + ni * 8 + (lane & 3) * 2;
                    sm[r0 * 129 + cc]           = c[mi][ni][0] + bias_s[cc];
                    sm[r0 * 129 + cc + 1]       = c[mi][ni][1] + bias_s[cc + 1];
                    sm[(r0 + 8) * 129 + cc]     = c[mi][ni][2] + bias_s[cc];
                    sm[(r0 + 8) * 129 + cc + 1] = c[mi][ni][3] + bias_s[cc + 1];
                }
            __syncthreads();

            const int b = m0 >> 11, h = n0 >> 7;
            if (z < 2) {
                __half* out = (z == 0) ? g_q16 : g_k16;
                const float qs = (z == 0) ? QSC : 1.0f;   // q pre-scaled for log2-softmax
                const long obase = ((long)(b * Hd + h) * Sd + (m0 & 2047)) * HDd;
                for (int idx = tid; idx < 128 * 64; idx += 256) {
                    const int r = idx >> 6, j = idx & 63;
                    const int s = (m0 & 2047) + r;
                    const float2 tc = g_rope[s * 64 + j];
                    const float lo = sm[r * 129 + j], hi = sm[r * 129 + j + 64];
                    out[obase + (long)r * HDd + j]      = __float2half((lo * tc.x - hi * tc.y) * qs);
                    out[obase + (long)r * HDd + j + 64] = __float2half((hi * tc.x + lo * tc.y) * qs);
                }
            } else {
                const long obase = (long)(b * Hd + h) * HDd * Sd;
                const int t0 = m0 & 2047;
                for (int idx = tid; idx < 128 * 128; idx += 256) {
                    const int hd = idx >> 7, tt = idx & 127;
                    g_vT16[obase + (long)hd * Sd + t0 + tt] = __float2half(sm[tt * 129 + hd]);
                }
            }
        }
    }
}

// ---------------------------------------------------------------------------
// Persistent fused flash attention (R11 3-stage, 1 barrier/iter).
// Softmax in log2 domain: scores arrive pre-scaled; exp via ex2.approx.f16x2.
// ---------------------------------------------------------------------------
#define PITCH 272
#define TILEB (128 * PITCH)          // 34816
#define FA_SMEM (6 * TILEB)          // 208896
#define FA_NT  (16 * BH)             // 512

__global__ void __launch_bounds__(256, 1) k_fattn() {
    extern __shared__ char smem[];
    const uint32_t sb = smem_to_u32(smem);
    const int tid = threadIdx.x, lane = tid & 31, w = tid >> 5;

    auto kbase = [&](int i) { return sb + (uint32_t)i * TILEB; };
    auto vbase = [&](int i) { return sb + (uint32_t)(3 + i) * TILEB; };

    auto ldtile = [&](uint32_t base, const __half* g, int ldg) {
#pragma unroll
        for (int it = 0; it < 8; it++) {
            const int id = tid + it * 256;
            const int row = id >> 4, ch = id & 15;
            uint32_t dst = base + (uint32_t)(row * PITCH + ch * 16);
            const __half* src = g + (long)row * ldg + ch * 8;
            asm volatile("cp.async.cg.shared.global [%0], [%1], 16;" :: "r"(dst), "l"(src));
        }
    };

    for (int t = blockIdx.x; t < FA_NT; t += gridDim.x) {
        const int m0 = (t & 15) * 128, bh = t >> 4;
        const __half* Qp = g_q16 + (long)bh * Sd * HDd + (long)m0 * HDd;
        const __half* Kp = g_k16 + (long)bh * Sd * HDd;
        const __half* Vp = g_vT16 + (long)bh * HDd * Sd;

        __syncthreads();
        ldtile(kbase(0), Qp, HDd);
        asm volatile("cp.async.commit_group;" ::: "memory");
        asm volatile("cp.async.wait_group 0;" ::: "memory");
        __syncthreads();

        uint32_t aq[8][4];
#pragma unroll
        for (int kk = 0; kk < 8; kk++) {
            const int row = w * 16 + (lane & 15);
            uint32_t ad = kbase(0) + (uint32_t)(row * PITCH + kk * 32 + ((lane >> 4) << 4));
            asm volatile("ldmatrix.sync.aligned.m8n8.x4.shared.b16 {%0,%1,%2,%3}, [%4];"
                         : "=r"(aq[kk][0]), "=r"(aq[kk][1]), "=r"(aq[kk][2]), "=r"(aq[kk][3])
                         : "r"(ad));
        }
        __syncthreads();

        float o[16][4] = {};
        float mr0 = -1e30f, mr1 = -1e30f, lr0 = 0.0f, lr1 = 0.0f;

        ldtile(kbase(0), Kp, HDd);
        ldtile(vbase(0), Vp, Sd);
        asm volatile("cp.async.commit_group;" ::: "memory");
        ldtile(kbase(1), Kp + (long)128 * HDd, HDd);
        ldtile(vbase(1), Vp + 128, Sd);
        asm volatile("cp.async.commit_group;" ::: "memory");

        for (int kt = 0; kt < 16; kt++) {
            const int buf = kt % 3;
            if (kt < 15) asm volatile("cp.async.wait_group 1;" ::: "memory");
            else         asm volatile("cp.async.wait_group 0;" ::: "memory");
            __syncthreads();

            // ---- S = Q K^T (already log2-scaled via q prescale) ----
            float cS[16][4] = {};
#pragma unroll
            for (int kk = 0; kk < 8; kk++) {
#pragma unroll
                for (int p = 0; p < 8; p++) {
                    const int g = lane >> 3;
                    const int row = p * 16 + (g >> 1) * 8 + (lane & 7);
                    uint32_t bd = kbase(buf) + (uint32_t)(row * PITCH + kk * 32 + ((g & 1) << 4));
                    uint32_t b0, b1, b2, b3;
                    asm volatile("ldmatrix.sync.aligned.m8n8.x4.shared.b16 {%0,%1,%2,%3}, [%4];"
                                 : "=r"(b0), "=r"(b1), "=r"(b2), "=r"(b3) : "r"(bd));
                    asm volatile(
                        "mma.sync.aligned.m16n8k16.row.col.f32.f16.f16.f32 "
                        "{%0,%1,%2,%3}, {%4,%5,%6,%7}, {%8,%9}, {%0,%1,%2,%3};"
                        : "+f"(cS[2*p][0]), "+f"(cS[2*p][1]), "+f"(cS[2*p][2]), "+f"(cS[2*p][3])
                        : "r"(aq[kk][0]), "r"(aq[kk][1]), "r"(aq[kk][2]), "r"(aq[kk][3]),
                          "r"(b0), "r"(b1));
                    asm volatile(
                        "mma.sync.aligned.m16n8k16.row.col.f32.f16.f16.f32 "
                        "{%0,%1,%2,%3}, {%4,%5,%6,%7}, {%8,%9}, {%0,%1,%2,%3};"
                        : "+f"(cS[2*p+1][0]), "+f"(cS[2*p+1][1]), "+f"(cS[2*p+1][2]), "+f"(cS[2*p+1][3])
                        : "r"(aq[kk][0]), "r"(aq[kk][1]), "r"(aq[kk][2]), "r"(aq[kk][3]),
                          "r"(b2), "r"(b3));
                }
            }

            // ---- online softmax (log2 domain, half2 ex2) ----
            float mx0 = -1e30f, mx1 = -1e30f;
#pragma unroll
            for (int ni = 0; ni < 16; ni++) {
                mx0 = fmaxf(mx0, fmaxf(cS[ni][0], cS[ni][1]));
                mx1 = fmaxf(mx1, fmaxf(cS[ni][2], cS[ni][3]));
            }
            mx0 = fmaxf(mx0, __shfl_xor_sync(0xffffffffu, mx0, 1));
            mx0 = fmaxf(mx0, __shfl_xor_sync(0xffffffffu, mx0, 2));
            mx1 = fmaxf(mx1, __shfl_xor_sync(0xffffffffu, mx1, 1));
            mx1 = fmaxf(mx1, __shfl_xor_sync(0xffffffffu, mx1, 2));

            const float mn0 = fmaxf(mr0, mx0), mn1 = fmaxf(mr1, mx1);
            const float al0 = exp2f(mr0 - mn0), al1 = exp2f(mr1 - mn1);
            mr0 = mn0; mr1 = mn1;

            uint32_t pr0[16], pr1[16];
            float s0 = 0.0f, s1 = 0.0f;
#pragma unroll
            for (int ni = 0; ni < 16; ni++) {
                __half2 d0 = __floats2half2_rn(cS[ni][0] - mn0, cS[ni][1] - mn0);
                __half2 d1 = __floats2half2_rn(cS[ni][2] - mn1, cS[ni][3] - mn1);
                uint32_t e0, e1;
                asm("ex2.approx.f16x2 %0, %1;" : "=r"(e0) : "r"(*(uint32_t*)&d0));
                asm("ex2.approx.f16x2 %0, %1;" : "=r"(e1) : "r"(*(uint32_t*)&d1));
                pr0[ni] = e0;
                pr1[ni] = e1;
                float2 f0 = __half22float2(*(__half2*)&e0);
                float2 f1 = __half22float2(*(__half2*)&e1);
                s0 += f0.x + f0.y;
                s1 += f1.x + f1.y;
            }
            s0 += __shfl_xor_sync(0xffffffffu, s0, 1);
            s0 += __shfl_xor_sync(0xffffffffu, s0, 2);
            s1 += __shfl_xor_sync(0xffffffffu, s1, 1);
            s1 += __shfl_xor_sync(0xffffffffu, s1, 2);
            lr0 = lr0 * al0 + s0;
            lr1 = lr1 * al1 + s1;

#pragma unroll
            for (int ni = 0; ni < 16; ni++) {
                o[ni][0] *= al0; o[ni][1] *= al0;
                o[ni][2] *= al1; o[ni][3] *= al1;
            }

            // ---- O += P V ----
#pragma unroll
            for (int kf = 0; kf < 8; kf++) {
                const uint32_t a0 = pr0[2 * kf], a1 = pr1[2 * kf];
                const uint32_t a2 = pr0[2 * kf + 1], a3 = pr1[2 * kf + 1];
#pragma unroll
                for (int p = 0; p < 8; p++) {
                    const int g = lane >> 3;
                    const int row = p * 16 + (g >> 1) * 8 + (lane & 7);
                    uint32_t bd = vbase(buf) + (uint32_t)(row * PITCH + kf * 32 + ((g & 1) << 4));
                    uint32_t b0, b1, b2, b3;
                    asm volatile("ldmatrix.sync.aligned.m8n8.x4.shared.b16 {%0,%1,%2,%3}, [%4];"
                                 : "=r"(b0), "=r"(b1), "=r"(b2), "=r"(b3) : "r"(bd));
                    asm volatile(
                        "mma.sync.aligned.m16n8k16.row.col.f32.f16.f16.f32 "
                        "{%0,%1,%2,%3}, {%4,%5,%6,%7}, {%8,%9}, {%0,%1,%2,%3};"
                        : "+f"(o[2*p][0]), "+f"(o[2*p][1]), "+f"(o[2*p][2]), "+f"(o[2*p][3])
                        : "r"(a0), "r"(a1), "r"(a2), "r"(a3), "r"(b0), "r"(b1));
                    asm volatile(
                        "mma.sync.aligned.m16n8k16.row.col.f32.f16.f16.f32 "
                        "{%0,%1,%2,%3}, {%4,%5,%6,%7}, {%8,%9}, {%0,%1,%2,%3};"
                        : "+f"(o[2*p+1][0]), "+f"(o[2*p+1][1]), "+f"(o[2*p+1][2]), "+f"(o[2*p+1][3])
                        : "r"(a0), "r"(a1), "r"(a2), "r"(a3), "r"(b2), "r"(b3));
                }
            }

            if (kt + 2 < 16) {
                const int nb = (kt + 2) % 3;
                ldtile(kbase(nb), Kp + (long)(kt + 2) * 128 * HDd, HDd);
                ldtile(vbase(nb), Vp + (kt + 2) * 128, Sd);
                asm volatile("cp.async.commit_group;" ::: "memory");
            }
        }

        // ---- epilogue ----
        const int b = bh >> 4, h = bh & 15;
        const float i0 = 1.0f / lr0, i1 = 1.0f / lr1;
        const int r0 = m0 + w * 16 + (lane >> 2);
        const long base0 = (long)b * Sd * Dd + (long)r0 * Dd + h * HDd + (lane & 3) * 2;
        const long base1 = base0 + 8 * Dd;
#pragma unroll
        for (int ni = 0; ni < 16; ni++) {
            __half2 h0 = __floats2half2_rn(o[ni][0] * i0, o[ni][1] * i0);
            __half2 h1 = __floats2half2_rn(o[ni][2] * i1, o[ni][3] * i1);
            *(__half2*)(g_ctx16 + base0 + ni * 8) = h0;
            *(__half2*)(g_ctx16 + base1 + ni * 8) = h1;
        }
    }
}

// ---------------------------------------------------------------------------
extern "C" void kernel_launch(void* const* d_in, const int* in_sizes, int n_in,
                              void* d_out, int out_size) {
    const float* hs = (const float*)d_in[0];
    const float* Wq = (const float*)d_in[1];
    const float* bq = (const float*)d_in[2];
    const float* Wk = (const float*)d_in[3];
    const float* bk = (const float*)d_in[4];
    const float* Wv = (const float*)d_in[5];
    const float* bv = (const float*)d_in[6];
    const float* Wo = (const float*)d_in[7];
    const float* bo = (const float*)d_in[8];
    float* out = (float*)d_out;

    static int sms = 0;
    if (!sms) {
        cudaDeviceGetAttribute(&sms, cudaDevAttrMultiProcessorCount, 0);
        cudaFuncSetAttribute(k_hgemm, cudaFuncAttributeMaxDynamicSharedMemorySize, GEMM_SMEM);
        cudaFuncSetAttribute(k_fattn, cudaFuncAttributeMaxDynamicSharedMemorySize, FA_SMEM);
    }

    k_prep<<<6656, 256>>>(hs, Wq, Wk, Wv, Wo);
    k_hgemm<<<2 * sms, 256, GEMM_SMEM>>>(bq, bk, bv, nullptr, 0, 1536);
    k_fattn<<<sms, 256, FA_SMEM>>>();
    k_hgemm<<<2 * sms, 256, GEMM_SMEM>>>(bo, nullptr, nullptr, out, 5, 512);
}